// round 7
// baseline (speedup 1.0000x reference)
#include <cuda_runtime.h>
#include <cuda_bf16.h>
#include <cstdint>

#define NROW 8192
#define DDIM 1024
#define CH 64                     // K per pipeline chunk (64 bf16 = 128 B)
#define KCH (DDIM / CH)           // 16 chunks
#define STAGES 4
#define TM 128                    // CTA tile M
#define TN 256                    // CTA tile N
#define NTM (NROW / TM)           // 64
#define NTN (NROW / TN)           // 32
#define STG_A (TM * 128)          // 16 KB
#define STG_B (TN * 128)          // 32 KB
#define STG_BYTES (STG_A + STG_B) // 48 KB
#define CHUNK_STRIDE ((size_t)NROW * 128)  // 1 MB per k-chunk blob
#define MARGINF 1.0f

// ---------------- device scratch ----------------
__device__ __nv_bfloat16 g_imgn[(size_t)NROW * DDIM];  // chunk-major swizzled, 16 MB
__device__ __nv_bfloat16 g_txtn[(size_t)NROW * DDIM];  // chunk-major swizzled, 16 MB
__device__ float g_pos[NROW];
__device__ float g_partial[(size_t)NTN * NROW];        // [ntile][row]

// ---------------- PTX helpers ----------------
__device__ __forceinline__ uint32_t smem_u32(const void* p) {
    uint32_t a;
    asm("{ .reg .u64 t; cvta.to.shared.u64 t, %1; cvt.u32.u64 %0, t; }" : "=r"(a) : "l"(p));
    return a;
}
__device__ __forceinline__ void mbar_init(uint32_t a, uint32_t c) {
    asm volatile("mbarrier.init.shared.b64 [%0], %1;" :: "r"(a), "r"(c) : "memory");
}
__device__ __forceinline__ void mbar_inval(uint32_t a) {
    asm volatile("mbarrier.inval.shared.b64 [%0];" :: "r"(a) : "memory");
}
__device__ __forceinline__ void mbar_expect_tx(uint32_t a, uint32_t tx) {
    asm volatile("mbarrier.arrive.expect_tx.shared.b64 _, [%0], %1;" :: "r"(a), "r"(tx) : "memory");
}
__device__ __forceinline__ void mbar_arrive(uint32_t a) {
    asm volatile("mbarrier.arrive.shared.b64 _, [%0];" :: "r"(a) : "memory");
}
__device__ __forceinline__ void mbar_wait(uint32_t a, uint32_t parity) {
    asm volatile(
        "{\n\t.reg .pred P;\n\t"
        "WL_%=:\n\t"
        "mbarrier.try_wait.parity.shared.b64 P, [%0], %1;\n\t"
        "@!P bra WL_%=;\n\t}"
        :: "r"(a), "r"(parity) : "memory");
}
__device__ __forceinline__ void bulk_g2s(uint32_t dst, const void* src, uint32_t bytes, uint32_t mbar) {
    asm volatile(
        "cp.async.bulk.shared::cluster.global.mbarrier::complete_tx::bytes [%0], [%1], %2, [%3];"
        :: "r"(dst), "l"(src), "r"(bytes), "r"(mbar) : "memory");
}
__device__ __forceinline__ void ldsm_x4(uint32_t& r0, uint32_t& r1, uint32_t& r2, uint32_t& r3,
                                        uint32_t addr) {
    asm volatile("ldmatrix.sync.aligned.m8n8.x4.shared.b16 {%0,%1,%2,%3}, [%4];"
                 : "=r"(r0), "=r"(r1), "=r"(r2), "=r"(r3) : "r"(addr));
}
__device__ __forceinline__ void mma16816(float& c0, float& c1, float& c2, float& c3,
                                         uint32_t a0, uint32_t a1, uint32_t a2, uint32_t a3,
                                         uint32_t b0, uint32_t b1) {
    asm volatile(
        "mma.sync.aligned.m16n8k16.row.col.f32.bf16.bf16.f32 "
        "{%0,%1,%2,%3}, {%4,%5,%6,%7}, {%8,%9}, {%0,%1,%2,%3};"
        : "+f"(c0), "+f"(c1), "+f"(c2), "+f"(c3)
        : "r"(a0), "r"(a1), "r"(a2), "r"(a3), "r"(b0), "r"(b1));
}

// ---------------------------------------------------------------------------
// Kernel 1: L2-normalize -> bf16 chunk-major swizzled + fp32 positives.
// WARP-PER-ROW: no block barriers, pure shfl reductions. 8 rows per CTA.
// ---------------------------------------------------------------------------
__global__ __launch_bounds__(256) void norm_kernel(const float* __restrict__ img,
                                                   const float* __restrict__ txt) {
    const int warp = threadIdx.x >> 5;
    const int lane = threadIdx.x & 31;
    const int row = blockIdx.x * 8 + warp;

    const float4* gA = reinterpret_cast<const float4*>(img + (size_t)row * DDIM);
    const float4* gB = reinterpret_cast<const float4*>(txt + (size_t)row * DDIM);

    float4 a[8], b[8];
    #pragma unroll
    for (int j = 0; j < 8; j++) {
        a[j] = gA[lane + j * 32];
        b[j] = gB[lane + j * 32];
    }

    float sii = 0.f, stt = 0.f, sit = 0.f;
    #pragma unroll
    for (int j = 0; j < 8; j++) {
        sii += a[j].x * a[j].x + a[j].y * a[j].y + a[j].z * a[j].z + a[j].w * a[j].w;
        stt += b[j].x * b[j].x + b[j].y * b[j].y + b[j].z * b[j].z + b[j].w * b[j].w;
        sit += a[j].x * b[j].x + a[j].y * b[j].y + a[j].z * b[j].z + a[j].w * b[j].w;
    }
    #pragma unroll
    for (int o = 16; o; o >>= 1) {
        sii += __shfl_xor_sync(0xffffffffu, sii, o);
        stt += __shfl_xor_sync(0xffffffffu, stt, o);
        sit += __shfl_xor_sync(0xffffffffu, sit, o);
    }

    const float inv_i = 1.0f / fmaxf(sqrtf(sii), 1e-12f);
    const float inv_t = 1.0f / fmaxf(sqrtf(stt), 1e-12f);

    #pragma unroll
    for (int j = 0; j < 8; j++) {
        __nv_bfloat162 i01 = __floats2bfloat162_rn(a[j].x * inv_i, a[j].y * inv_i);
        __nv_bfloat162 i23 = __floats2bfloat162_rn(a[j].z * inv_i, a[j].w * inv_i);
        __nv_bfloat162 t01 = __floats2bfloat162_rn(b[j].x * inv_t, b[j].y * inv_t);
        __nv_bfloat162 t23 = __floats2bfloat162_rn(b[j].z * inv_t, b[j].w * inv_t);

        uint2 pi, pt;
        pi.x = *reinterpret_cast<unsigned int*>(&i01);
        pi.y = *reinterpret_cast<unsigned int*>(&i23);
        pt.x = *reinterpret_cast<unsigned int*>(&t01);
        pt.y = *reinterpret_cast<unsigned int*>(&t23);

        const int f = lane + j * 32;          // float4 index within row
        const int c = f >> 4;                 // k-chunk (16 float4 = 64 cols)
        const int ci = (f & 15) << 2;         // col within chunk (4 bf16)
        uint32_t off = (uint32_t)row * 128u + (uint32_t)ci * 2u;
        off ^= (off >> 3) & 0x70u;
        const size_t addr = (size_t)c * CHUNK_STRIDE + off;

        *reinterpret_cast<uint2*>(reinterpret_cast<char*>(g_imgn) + addr) = pi;
        *reinterpret_cast<uint2*>(reinterpret_cast<char*>(g_txtn) + addr) = pt;
    }

    if (lane == 0) g_pos[row] = sit * inv_i * inv_t;  // exact fp32 diagonal
}

// ---------------------------------------------------------------------------
// Kernel 2: bulk-async 4-stage mma.sync bf16 GEMM + fused exp(sim-1) rowsum.
// (unchanged from R6 -- 92% of HMMA issue floor)
// ---------------------------------------------------------------------------
__global__ __launch_bounds__(256, 1) void gemm_lse_kernel() {
    extern __shared__ __align__(128) char smem[];       // STAGES*48KB (+pad)
    __shared__ __align__(8) unsigned long long full_bar[STAGES], empty_bar[STAGES];
    __shared__ float rowAcc[TM];

    const int tid = threadIdx.x;
    const int warp = tid >> 5;
    const int lane = tid & 31;
    const int wm = warp >> 2;        // 0..1
    const int wn = warp & 3;         // 0..3
    const int mtile = blockIdx.x;    // 64
    const int ntile = blockIdx.y;    // 32

    uint32_t sbase = smem_u32(smem);
    sbase = (sbase + 127u) & ~127u;
    const uint32_t fullb = smem_u32(&full_bar[0]);
    const uint32_t emptyb = smem_u32(&empty_bar[0]);

    if (tid == 0) {
        #pragma unroll
        for (int s = 0; s < STAGES; s++) {
            mbar_init(fullb + 8u * s, 1);
            mbar_init(emptyb + 8u * s, 8);   // one arrive per warp
        }
    }
    if (tid < TM) rowAcc[tid] = 0.0f;
    __syncthreads();

    const char* baseA = reinterpret_cast<const char*>(g_imgn) + (size_t)mtile * STG_A;
    const char* baseB = reinterpret_cast<const char*>(g_txtn) + (size_t)ntile * STG_B;

    if (tid == 0) {
        #pragma unroll
        for (int c = 0; c < STAGES - 1; c++) {
            const uint32_t st = sbase + (uint32_t)c * STG_BYTES;
            mbar_expect_tx(fullb + 8u * c, STG_BYTES);
            bulk_g2s(st,         baseA + (size_t)c * CHUNK_STRIDE, STG_A, fullb + 8u * c);
            bulk_g2s(st + STG_A, baseB + (size_t)c * CHUNK_STRIDE, STG_B, fullb + 8u * c);
        }
    }

    float acc[4][8][4];
    #pragma unroll
    for (int mi = 0; mi < 4; mi++)
        #pragma unroll
        for (int ni = 0; ni < 8; ni++)
            #pragma unroll
            for (int e = 0; e < 4; e++) acc[mi][ni][e] = 0.0f;

    #pragma unroll 4
    for (int c = 0; c < KCH; c++) {
        const int s = c & (STAGES - 1);
        mbar_wait(fullb + 8u * s, (uint32_t)((c >> 2) & 1));

        const uint32_t sa = sbase + (uint32_t)s * STG_BYTES;
        const uint32_t sb = sa + STG_A;

        #pragma unroll
        for (int ks = 0; ks < 4; ks++) {
            uint32_t a[4][4], b[4][4];
            #pragma unroll
            for (int mi = 0; mi < 4; mi++) {
                const int r = wm * 64 + mi * 16 + (lane & 15);
                const int g = 2 * ks + (lane >> 4);
                ldsm_x4(a[mi][0], a[mi][1], a[mi][2], a[mi][3],
                        sa + (uint32_t)r * 128u + (uint32_t)((g ^ (r & 7)) << 4));
            }
            #pragma unroll
            for (int bi = 0; bi < 4; bi++) {
                const int nr = wn * 64 + bi * 16 + (lane & 7) + ((lane >> 4) << 3);
                const int g = 2 * ks + ((lane >> 3) & 1);
                ldsm_x4(b[bi][0], b[bi][1], b[bi][2], b[bi][3],
                        sb + (uint32_t)nr * 128u + (uint32_t)((g ^ (nr & 7)) << 4));
            }
            #pragma unroll
            for (int mi = 0; mi < 4; mi++)
                #pragma unroll
                for (int ni = 0; ni < 8; ni++)
                    mma16816(acc[mi][ni][0], acc[mi][ni][1], acc[mi][ni][2], acc[mi][ni][3],
                             a[mi][0], a[mi][1], a[mi][2], a[mi][3],
                             b[ni >> 1][(ni & 1) * 2], b[ni >> 1][(ni & 1) * 2 + 1]);
        }

        if (lane == 0) mbar_arrive(emptyb + 8u * s);

        if (tid == 0) {
            const int nx = c + STAGES - 1;
            if (nx < KCH) {
                const int sn = nx & (STAGES - 1);
                if (nx >= STAGES)
                    mbar_wait(emptyb + 8u * sn, (uint32_t)(((nx >> 2) - 1) & 1));
                const uint32_t st = sbase + (uint32_t)sn * STG_BYTES;
                mbar_expect_tx(fullb + 8u * sn, STG_BYTES);
                bulk_g2s(st,         baseA + (size_t)nx * CHUNK_STRIDE, STG_A, fullb + 8u * sn);
                bulk_g2s(st + STG_A, baseB + (size_t)nx * CHUNK_STRIDE, STG_B, fullb + 8u * sn);
            }
        }
    }

    // Epilogue: exp(sim - margin), per-row reduce (quad shfl + smem atomics)
    #pragma unroll
    for (int mi = 0; mi < 4; mi++) {
        float s0 = 0.0f, s1 = 0.0f;
        #pragma unroll
        for (int ni = 0; ni < 8; ni++) {
            s0 += __expf(acc[mi][ni][0] - MARGINF) + __expf(acc[mi][ni][1] - MARGINF);
            s1 += __expf(acc[mi][ni][2] - MARGINF) + __expf(acc[mi][ni][3] - MARGINF);
        }
        s0 += __shfl_xor_sync(0xffffffffu, s0, 1);
        s0 += __shfl_xor_sync(0xffffffffu, s0, 2);
        s1 += __shfl_xor_sync(0xffffffffu, s1, 1);
        s1 += __shfl_xor_sync(0xffffffffu, s1, 2);
        if ((lane & 3) == 0) {
            const int r = wm * 64 + mi * 16 + (lane >> 2);
            atomicAdd(&rowAcc[r], s0);
            atomicAdd(&rowAcc[r + 8], s1);
        }
    }
    __syncthreads();
    if (tid < TM)
        g_partial[(size_t)ntile * NROW + mtile * TM + tid] = rowAcc[tid];

    if (tid == 0) {
        #pragma unroll
        for (int s = 0; s < STAGES; s++) {
            mbar_inval(fullb + 8u * s);
            mbar_inval(emptyb + 8u * s);
        }
    }
}

// ---------------------------------------------------------------------------
// Kernel 3: fused finalize. Single CTA, 1024 threads, 8 rows/thread:
// lse_row = log(sum_p partial[p][row]) - pos[row]; out = mean (fixed-order).
// ---------------------------------------------------------------------------
__global__ __launch_bounds__(1024) void finalize_kernel(float* __restrict__ out) {
    __shared__ float red[1024];
    float tsum = 0.0f;
    #pragma unroll
    for (int i = 0; i < NROW / 1024; i++) {
        const int row = threadIdx.x + i * 1024;
        float s = 0.0f;
        #pragma unroll
        for (int p = 0; p < NTN; p++) s += g_partial[(size_t)p * NROW + row];
        tsum += logf(s) - g_pos[row];
    }
    red[threadIdx.x] = tsum;
    __syncthreads();
    #pragma unroll
    for (int off = 512; off > 0; off >>= 1) {
        if (threadIdx.x < off) red[threadIdx.x] += red[threadIdx.x + off];
        __syncthreads();
    }
    if (threadIdx.x == 0) out[0] = red[0] / (float)NROW;
}

// ---------------------------------------------------------------------------
extern "C" void kernel_launch(void* const* d_in, const int* in_sizes, int n_in,
                              void* d_out, int out_size) {
    const float* img = (const float*)d_in[0];
    const float* txt = (const float*)d_in[1];
    float* out = (float*)d_out;

    norm_kernel<<<NROW / 8, 256>>>(img, txt);

    cudaFuncSetAttribute(gemm_lse_kernel,
                         cudaFuncAttributeMaxDynamicSharedMemorySize,
                         STAGES * STG_BYTES + 128);
    dim3 grid(NTM, NTN);
    gemm_lse_kernel<<<grid, 256, STAGES * STG_BYTES + 128>>>();

    finalize_kernel<<<1, 1024>>>(out);
}